// round 3
// baseline (speedup 1.0000x reference)
#include <cuda_runtime.h>

// QuantumKernelLayer collapsed to 6 cosines/sample:
//   a = x0+p0, b = x1+p1
//   z0 = 0.5*[(1-sin b)*cos(p2-a) + (1+sin b)*cos(p2+a)]
//   z1 = 0.5*[cos(a)*(cos(p3-b)+cos(p3+b)) - (cos(p3-b)-cos(p3+b))]
// HBM-streaming bound at ~6.4 TB/s aggregate. Read-once/write-once:
// use streaming (evict-first) cache hints on all traffic.

__device__ __forceinline__ float2 qkl_one(float x0, float x1,
                                          float p0, float p1,
                                          float p2, float p3)
{
    float a = x0 + p0;
    float b = x1 + p1;

    float cu = __cosf(p2 - a);
    float cv = __cosf(p2 + a);
    float sb = __sinf(b);
    float ca = __cosf(a);
    float cw = __cosf(p3 - b);
    float ct = __cosf(p3 + b);

    float z0 = 0.5f * ((1.0f - sb) * cu + (1.0f + sb) * cv);
    float z1 = 0.5f * (ca * (cw + ct) - (cw - ct));
    return make_float2(z0, z1);
}

__global__ __launch_bounds__(512)
void qkl_kernel4s(const float4* __restrict__ x2,  // 2 samples per float4
                  const float4* __restrict__ p1v, // 1 sample per float4
                  float4* __restrict__ o2,        // 2 samples per float4
                  int n)                          // total samples
{
    int i = blockIdx.x * blockDim.x + threadIdx.x;  // group of 4 samples
    int s = i * 4;

    if (s + 4 <= n) {
        // Front-batched streaming loads: 6 independent LDG.E.128 (evict-first)
        float4 xa = __ldcs(&x2[2 * i]);
        float4 xb = __ldcs(&x2[2 * i + 1]);
        float4 pa = __ldcs(&p1v[4 * i]);
        float4 pb = __ldcs(&p1v[4 * i + 1]);
        float4 pc = __ldcs(&p1v[4 * i + 2]);
        float4 pd = __ldcs(&p1v[4 * i + 3]);

        float2 r0 = qkl_one(xa.x, xa.y, pa.x, pa.y, pa.z, pa.w);
        float2 r1 = qkl_one(xa.z, xa.w, pb.x, pb.y, pb.z, pb.w);
        float2 r2 = qkl_one(xb.x, xb.y, pc.x, pc.y, pc.z, pc.w);
        float2 r3 = qkl_one(xb.z, xb.w, pd.x, pd.y, pd.z, pd.w);

        __stcs(&o2[2 * i],     make_float4(r0.x, r0.y, r1.x, r1.y));
        __stcs(&o2[2 * i + 1], make_float4(r2.x, r2.y, r3.x, r3.y));
    } else if (s < n) {
        // Scalar tail (never taken for B=4194304, kept for safety)
        const float* xf = (const float*)x2;
        const float* pf = (const float*)p1v;
        float* of = (float*)o2;
        for (int k = s; k < n; k++) {
            float2 r = qkl_one(xf[2 * k], xf[2 * k + 1],
                               pf[4 * k], pf[4 * k + 1],
                               pf[4 * k + 2], pf[4 * k + 3]);
            of[2 * k] = r.x;
            of[2 * k + 1] = r.y;
        }
    }
}

extern "C" void kernel_launch(void* const* d_in, const int* in_sizes, int n_in,
                              void* d_out, int out_size)
{
    const float4* x = (const float4*)d_in[0];   // x: [B,2] float32
    const float4* p = (const float4*)d_in[1];   // parameters: [B,4] float32
    float4* out = (float4*)d_out;               // out: [B,2] float32

    int n = in_sizes[0] / 2;                    // B samples
    int threads = 512;
    int groups = (n + 3) / 4;
    int blocks = (groups + threads - 1) / threads;
    qkl_kernel4s<<<blocks, threads>>>(x, p, out, n);
}

// round 4
// speedup vs baseline: 1.0918x; 1.0918x over previous
#include <cuda_runtime.h>

// QuantumKernelLayer collapsed to 6 cosines/sample:
//   a = x0+p0, b = x1+p1
//   z0 = 0.5*[(1-sin b)*cos(p2-a) + (1+sin b)*cos(p2+a)]
//   z1 = 0.5*[cos(a)*(cos(p3-b)+cos(p3+b)) - (cos(p3-b)-cos(p3+b))]
// HBM-streaming bound. ILP=2 / low-register variant: maximize resident
// warps (target 100% occupancy) to raise chip-wide MLP and DRAM
// cycles-active. Default cache ops (streaming hints measured neutral).

__device__ __forceinline__ float2 qkl_one(float x0, float x1,
                                          float p0, float p1,
                                          float p2, float p3)
{
    float a = x0 + p0;
    float b = x1 + p1;

    float cu = __cosf(p2 - a);
    float cv = __cosf(p2 + a);
    float sb = __sinf(b);
    float ca = __cosf(a);
    float cw = __cosf(p3 - b);
    float ct = __cosf(p3 + b);

    float z0 = 0.5f * ((1.0f - sb) * cu + (1.0f + sb) * cv);
    float z1 = 0.5f * (ca * (cw + ct) - (cw - ct));
    return make_float2(z0, z1);
}

__global__ __launch_bounds__(256)
void qkl_kernel2(const float4* __restrict__ x2,  // 2 samples per float4
                 const float4* __restrict__ p1v, // 1 sample per float4
                 float4* __restrict__ o2,        // 2 samples per float4
                 int n)                          // total samples
{
    int i = blockIdx.x * blockDim.x + threadIdx.x;  // group of 2 samples
    int s = i * 2;

    if (s + 2 <= n) {
        // Front-batched loads: 3 independent LDG.128
        float4 xa = x2[i];
        float4 pa = p1v[2 * i];
        float4 pb = p1v[2 * i + 1];

        float2 r0 = qkl_one(xa.x, xa.y, pa.x, pa.y, pa.z, pa.w);
        float2 r1 = qkl_one(xa.z, xa.w, pb.x, pb.y, pb.z, pb.w);

        o2[i] = make_float4(r0.x, r0.y, r1.x, r1.y);
    } else if (s < n) {
        // Scalar tail (never taken for B=4194304, kept for safety)
        const float* xf = (const float*)x2;
        const float* pf = (const float*)p1v;
        float* of = (float*)o2;
        for (int k = s; k < n; k++) {
            float2 r = qkl_one(xf[2 * k], xf[2 * k + 1],
                               pf[4 * k], pf[4 * k + 1],
                               pf[4 * k + 2], pf[4 * k + 3]);
            of[2 * k] = r.x;
            of[2 * k + 1] = r.y;
        }
    }
}

extern "C" void kernel_launch(void* const* d_in, const int* in_sizes, int n_in,
                              void* d_out, int out_size)
{
    const float4* x = (const float4*)d_in[0];   // x: [B,2] float32
    const float4* p = (const float4*)d_in[1];   // parameters: [B,4] float32
    float4* out = (float4*)d_out;               // out: [B,2] float32

    int n = in_sizes[0] / 2;                    // B samples
    int threads = 256;
    int groups = (n + 1) / 2;
    int blocks = (groups + threads - 1) / threads;
    qkl_kernel2<<<blocks, threads>>>(x, p, out, n);
}